// round 17
// baseline (speedup 1.0000x reference)
#include <cuda_runtime.h>

// PixelWiseRNN: h_t = tanh(w_ih*x_t + b_ih + w_hh*h_{t-1} + b_hh), h_0 = 0
// x: (B, T, Z, H, W) fp32, params: (Z, H, W) fp32, out: (B, T, Z, H, W) fp32
// B=4, T=256, Z=16, H=64, W=64  ->  P = Z*H*W = 65536 pixels per batch.
//
// R16: width axis, final doubling. float4 (LDG.128/STG.128): halves LSU ops
// and L1tex queue requests again vs float2. Unlike R1's failed float4 (tanhf
// long chain + manual depth-2 pipeline), this keeps 4 independent MUFU.TANH
// chains per thread -> 13.8 warps/SM x 4 = 55 chain contexts, same hiding
// capacity as every winning shape. 64-thread blocks -> 1024 CTAs (6.9/SM
// wave balance). unroll 8, ptxas front-batches the loads.

#define RNN_B  4
#define RNN_T  256
#define RNN_P  65536          // Z*H*W
#define RNN_NV (RNN_P / 4)    // 16384 float4 vectors per batch slice

__device__ __forceinline__ float hw_tanh(float z)
{
    float r;
    asm("tanh.approx.f32 %0, %1;" : "=f"(r) : "f"(z));
    return r;
}

__global__ __launch_bounds__(64) void pixel_rnn_kernel(
    const float* __restrict__ x,
    const float* __restrict__ w_ih,
    const float* __restrict__ w_hh,
    const float* __restrict__ b_ih,
    const float* __restrict__ b_hh,
    float* __restrict__ out)
{
    const int gid = blockIdx.x * blockDim.x + threadIdx.x;  // [0, B*NV) = 65536
    const int b = gid >> 14;            // gid / NV
    const int v = gid & (RNN_NV - 1);   // gid % NV
    const int p = v << 2;               // first of 4 adjacent pixels

    const float4 wi = *(const float4*)(w_ih + p);
    const float4 wh = *(const float4*)(w_hh + p);
    const float4 bi = *(const float4*)(b_ih + p);
    const float4 bh = *(const float4*)(b_hh + p);
    const float4 bias = make_float4(bi.x + bh.x, bi.y + bh.y,
                                    bi.z + bh.z, bi.w + bh.w);

    const size_t base = (size_t)b * RNN_T * RNN_P + p;
    const float4* __restrict__ xp = (const float4*)(x + base);
    float4* __restrict__ op = (float4*)(out + base);
    const int stride = RNN_P / 4;       // per-timestep stride in float4 units

    float4 h  = make_float4(0.f, 0.f, 0.f, 0.f);
    float4 xv = xp[0];   // prefetched x_0

    #pragma unroll 8
    for (int t = 0; t < RNN_T; t++) {
        // Prefetch next x off the dependency chain (clamped at the end).
        const int tn = (t + 1 < RNN_T) ? (t + 1) : t;
        const float4 xn = xp[(size_t)tn * stride];

        // Off-chain: a = wi*x + bias (independent of h). Four independent
        // chains interleave through the FMA/MUFU pipes.
        const float ax = fmaf(wi.x, xv.x, bias.x);
        const float ay = fmaf(wi.y, xv.y, bias.y);
        const float az = fmaf(wi.z, xv.z, bias.z);
        const float aw = fmaf(wi.w, xv.w, bias.w);
        h.x = hw_tanh(fmaf(wh.x, h.x, ax));
        h.y = hw_tanh(fmaf(wh.y, h.y, ay));
        h.z = hw_tanh(fmaf(wh.z, h.z, az));
        h.w = hw_tanh(fmaf(wh.w, h.w, aw));

        op[(size_t)t * stride] = h;
        xv = xn;
    }
}

extern "C" void kernel_launch(void* const* d_in, const int* in_sizes, int n_in,
                              void* d_out, int out_size)
{
    const float* x    = (const float*)d_in[0];
    const float* w_ih = (const float*)d_in[1];
    const float* w_hh = (const float*)d_in[2];
    const float* b_ih = (const float*)d_in[3];
    const float* b_hh = (const float*)d_in[4];
    float* out = (float*)d_out;

    const int total_threads = RNN_B * RNN_NV;  // 65536
    const int block = 64;
    const int grid = total_threads / block;    // 1024

    pixel_rnn_kernel<<<grid, block>>>(x, w_ih, w_hh, b_ih, b_hh, out);
}